// round 1
// baseline (speedup 1.0000x reference)
#include <cuda_runtime.h>
#include <cuda_bf16.h>

// Viterbi detector: 16-state trellis collapsed to 8 effective states
// (tt[s] == tt[s+8]  =>  out_prob[s] == out_prob[s+8] exactly).
//
// Round 1: rounding-faithful sequential scan, one thread per row.
// All fp ops via *_rn intrinsics to forbid contraction/reassociation so the
// fp32 rounding sequence matches the straightforward XLA lowering:
//   d = y - sp; t = d*d; prior = t*0.5 - C; m = q + prior; min pairs; argmin-first.

#define T_LEN 4096
#define B_ROWS 2048
#define NEG_LOG_SQRT_2PI (-0.9189385332046727f)

__device__ __forceinline__ float vstep(float (&q)[8], const float (&spn)[16], float yt) {
    // decoded bit for this step: parity of first argmin over the 8 carried
    // metrics (states 8..15 duplicate 0..7 with identical bits, so the first
    // minimum of the 16-state vector always lands in 0..7).
    float best = q[0];
    float par = 0.0f;
#pragma unroll
    for (int k = 1; k < 8; k++) {
        bool lt = q[k] < best;            // strict < keeps first-index semantics
        par  = lt ? (float)(k & 1) : par;
        best = lt ? q[k] : best;
    }

    float m[16];
#pragma unroll
    for (int j = 0; j < 16; j++) {
        float dd = __fadd_rn(yt, spn[j]);                       // y - sp[j]
        float t2 = __fmul_rn(dd, dd);                           // (y-sp)^2
        float pr = __fmaf_rn(t2, 0.5f, NEG_LOG_SQRT_2PI);       // == t2/2 - C exactly
        m[j] = __fadd_rn(q[j & 7], pr);                         // in_prob + prior
    }
#pragma unroll
    for (int k = 0; k < 8; k++) {
        // out_prob[k] = min(m[2k], m[2k+1])  (tt[k] = [2k, 2k+1] for k<8)
        q[k] = fminf(m[2 * k], m[2 * k + 1]);
    }
    return par;
}

__global__ void __launch_bounds__(32, 1)
viterbi_seq_kernel(const float* __restrict__ y,
                   const float* __restrict__ h,
                   float* __restrict__ out) {
    int row = blockIdx.x * 32 + threadIdx.x;
    if (row >= B_ROWS) return;

    // sp[s] = sum_j symbols[s,j] * h[j], symbols = +-1 (products exact),
    // summed left-to-right like a naive small dot. Store negated.
    float h0 = h[0], h1 = h[1], h2 = h[2], h3 = h[3];
    float spn[16];
#pragma unroll
    for (int s = 0; s < 16; s++) {
        float s3 = ((s >> 3) & 1) ? -1.0f : 1.0f;  // MSB first (shifts = 3,2,1,0)
        float s2 = ((s >> 2) & 1) ? -1.0f : 1.0f;
        float s1 = ((s >> 1) & 1) ? -1.0f : 1.0f;
        float s0 = ((s >> 0) & 1) ? -1.0f : 1.0f;
        float sp = __fadd_rn(
                       __fadd_rn(
                           __fadd_rn(__fmul_rn(s3, h0), __fmul_rn(s2, h1)),
                           __fmul_rn(s1, h2)),
                       __fmul_rn(s0, h3));
        spn[s] = -sp;
    }

    float q[8];
#pragma unroll
    for (int k = 0; k < 8; k++) q[k] = 0.0f;

    const float4* yv = reinterpret_cast<const float4*>(y + (size_t)row * T_LEN);
    float4*       ov = reinterpret_cast<float4*>(out + (size_t)row * T_LEN);

#pragma unroll 1
    for (int i = 0; i < T_LEN / 4; i++) {
        float4 yy = yv[i];
        float4 d;
        d.x = vstep(q, spn, yy.x);
        d.y = vstep(q, spn, yy.y);
        d.z = vstep(q, spn, yy.z);
        d.w = vstep(q, spn, yy.w);
        ov[i] = d;
    }
}

extern "C" void kernel_launch(void* const* d_in, const int* in_sizes, int n_in,
                              void* d_out, int out_size) {
    const float* y = (const float*)d_in[0];
    const float* h = (const float*)d_in[1];
    // d_in[2] = transition_table: fixed trellis tt[s] = [2s%16, (2s+1)%16], hardcoded.
    float* out = (float*)d_out;
    viterbi_seq_kernel<<<B_ROWS / 32, 32>>>(y, h, out);
}

// round 2
// speedup vs baseline: 1.1926x; 1.1926x over previous
#include <cuda_runtime.h>
#include <cuda_bf16.h>

// 16-state Viterbi, collapsed to 8 carried metrics (tt[s]==tt[s+8]).
// Round 2: states packed pairwise into f32x2; priors/metrics via packed
// add/mul/fma.rn.f32x2 (bit-exact: two independent rn-rounded fp32 ops).
// Tree argmin with left-priority strict-< == jnp.argmin first-index.

#define T_LEN 4096
#define B_ROWS 2048
#define NEG_LOG_SQRT_2PI (-0.9189385332046727f)

typedef unsigned long long u64;

__device__ __forceinline__ u64 pk2(float lo, float hi) {
    u64 r; asm("mov.b64 %0, {%1, %2};" : "=l"(r) : "f"(lo), "f"(hi)); return r;
}
__device__ __forceinline__ void upk2(u64 v, float& lo, float& hi) {
    asm("mov.b64 {%0, %1}, %2;" : "=f"(lo), "=f"(hi) : "l"(v));
}
__device__ __forceinline__ u64 add2(u64 a, u64 b) {
    u64 r; asm("add.rn.f32x2 %0, %1, %2;" : "=l"(r) : "l"(a), "l"(b)); return r;
}
__device__ __forceinline__ u64 mul2(u64 a, u64 b) {
    u64 r; asm("mul.rn.f32x2 %0, %1, %2;" : "=l"(r) : "l"(a), "l"(b)); return r;
}
__device__ __forceinline__ u64 fma2(u64 a, u64 b, u64 c) {
    u64 r; asm("fma.rn.f32x2 %0, %1, %2, %3;" : "=l"(r) : "l"(a), "l"(b), "l"(c)); return r;
}

// One trellis step. q[0..7] = scalar carried metrics, qp[0..3] = packed pairs
// (q0,q1)(q2,q3)(q4,q5)(q6,q7). spn2[i] = (-sp[2i], -sp[2i+1]).
// Returns decoded parity for this step (argmin of q BEFORE the update).
__device__ __forceinline__ float vstep(float (&q)[8], u64 (&qp)[4],
                                       const u64 (&spn2)[8],
                                       u64 half2, u64 negc2, float yt) {
    // ---- decoded bit: first-argmin parity over current q (depth-3 tree) ----
    float p01 = (q[1] < q[0]) ? 1.0f : 0.0f;  float v01 = fminf(q[0], q[1]);
    float p23 = (q[3] < q[2]) ? 1.0f : 0.0f;  float v23 = fminf(q[2], q[3]);
    float p45 = (q[5] < q[4]) ? 1.0f : 0.0f;  float v45 = fminf(q[4], q[5]);
    float p67 = (q[7] < q[6]) ? 1.0f : 0.0f;  float v67 = fminf(q[6], q[7]);
    float pa  = (v23 < v01) ? p23 : p01;      float va  = fminf(v01, v23);
    float pb  = (v67 < v45) ? p67 : p45;      float vb  = fminf(v45, v67);
    float par = (vb  < va)  ? pb  : pa;

    // ---- metric update ----
    u64 y2 = pk2(yt, yt);
    u64 m[8];
#pragma unroll
    for (int i = 0; i < 8; i++) {
        u64 dd = add2(y2, spn2[i]);            // y - sp  (two states at once)
        u64 t2 = mul2(dd, dd);                 // (y-sp)^2
        u64 pr = fma2(t2, half2, negc2);       // exact t2*0.5, single rn on -C
        m[i]   = add2(qp[i & 3], pr);          // in_prob + prior
    }
#pragma unroll
    for (int k = 0; k < 8; k++) {
        float a, b; upk2(m[k], a, b);          // m[2k], m[2k+1]
        q[k] = fminf(a, b);
    }
#pragma unroll
    for (int j = 0; j < 4; j++) qp[j] = pk2(q[2 * j], q[2 * j + 1]);

    return par;
}

__global__ void __launch_bounds__(32, 1)
viterbi_seq_kernel(const float* __restrict__ y,
                   const float* __restrict__ h,
                   float* __restrict__ out) {
    int row = blockIdx.x * 32 + threadIdx.x;
    if (row >= B_ROWS) return;

    float h0 = h[0], h1 = h[1], h2 = h[2], h3 = h[3];
    float spn[16];
#pragma unroll
    for (int s = 0; s < 16; s++) {
        float s3 = ((s >> 3) & 1) ? -1.0f : 1.0f;  // MSB first (shifts 3,2,1,0)
        float s2 = ((s >> 2) & 1) ? -1.0f : 1.0f;
        float s1 = ((s >> 1) & 1) ? -1.0f : 1.0f;
        float s0 = ((s >> 0) & 1) ? -1.0f : 1.0f;
        float sp = __fadd_rn(
                       __fadd_rn(
                           __fadd_rn(__fmul_rn(s3, h0), __fmul_rn(s2, h1)),
                           __fmul_rn(s1, h2)),
                       __fmul_rn(s0, h3));
        spn[s] = -sp;
    }
    u64 spn2[8];
#pragma unroll
    for (int i = 0; i < 8; i++) spn2[i] = pk2(spn[2 * i], spn[2 * i + 1]);
    u64 half2 = pk2(0.5f, 0.5f);
    u64 negc2 = pk2(NEG_LOG_SQRT_2PI, NEG_LOG_SQRT_2PI);

    float q[8];
    u64 qp[4];
#pragma unroll
    for (int k = 0; k < 8; k++) q[k] = 0.0f;
#pragma unroll
    for (int j = 0; j < 4; j++) qp[j] = pk2(0.0f, 0.0f);

    const float4* yv = reinterpret_cast<const float4*>(y + (size_t)row * T_LEN);
    float4*       ov = reinterpret_cast<float4*>(out + (size_t)row * T_LEN);

#pragma unroll 1
    for (int i = 0; i < T_LEN / 4; i++) {
        float4 yy = yv[i];
        float4 d;
        d.x = vstep(q, qp, spn2, half2, negc2, yy.x);
        d.y = vstep(q, qp, spn2, half2, negc2, yy.y);
        d.z = vstep(q, qp, spn2, half2, negc2, yy.z);
        d.w = vstep(q, qp, spn2, half2, negc2, yy.w);
        ov[i] = d;
    }
}

extern "C" void kernel_launch(void* const* d_in, const int* in_sizes, int n_in,
                              void* d_out, int out_size) {
    const float* y = (const float*)d_in[0];
    const float* h = (const float*)d_in[1];
    // d_in[2] = transition_table: fixed trellis tt[s] = [2s%16, (2s+1)%16], hardcoded.
    float* out = (float*)d_out;
    viterbi_seq_kernel<<<B_ROWS / 32, 32>>>(y, h, out);
}

// round 4
// speedup vs baseline: 1.3263x; 1.1121x over previous
#include <cuda_runtime.h>
#include <cuda_bf16.h>

// 16-state Viterbi, 8 carried metrics (tt[s]==tt[s+8]).
// Round 4 (= Round 3 resubmit + load prefetch): two lanes per row.
// Even lane owns q0..3, odd lane q4..7. Per step each lane updates its half
// (8 trellis states, packed f32x2), exchanges one metric pair + argmin
// partials via shfl.xor(1). All fp ops bit-identical to the verified
// sequential version (rel_err==0).

#define T_LEN 4096
#define B_ROWS 2048
#define NEG_LOG_SQRT_2PI (-0.9189385332046727f)

typedef unsigned long long u64;

__device__ __forceinline__ u64 pk2(float lo, float hi) {
    u64 r; asm("mov.b64 %0, {%1, %2};" : "=l"(r) : "f"(lo), "f"(hi)); return r;
}
__device__ __forceinline__ void upk2(u64 v, float& lo, float& hi) {
    asm("mov.b64 {%0, %1}, %2;" : "=f"(lo), "=f"(hi) : "l"(v));
}
__device__ __forceinline__ u64 add2(u64 a, u64 b) {
    u64 r; asm("add.rn.f32x2 %0, %1, %2;" : "=l"(r) : "l"(a), "l"(b)); return r;
}
__device__ __forceinline__ u64 mul2(u64 a, u64 b) {
    u64 r; asm("mul.rn.f32x2 %0, %1, %2;" : "=l"(r) : "l"(a), "l"(b)); return r;
}
__device__ __forceinline__ u64 fma2(u64 a, u64 b, u64 c) {
    u64 r; asm("fma.rn.f32x2 %0, %1, %2, %3;" : "=l"(r) : "l"(a), "l"(b), "l"(c)); return r;
}
__device__ __forceinline__ float shflx(float v) {
    return __shfl_xor_sync(0xffffffffu, v, 1, 32);
}

// One trellis step for one lane (half=0: q0..3 / states 0..7;
// half=1: q4..7 / states 8..15's m-values). Returns decoded parity
// (valid on even lanes).
__device__ __forceinline__ float vstep(u64& qpA, u64& qpB,
                                       u64 sp0, u64 sp1, u64 sp4, u64 sp5,
                                       u64 half2, u64 negc2, int half, float yt) {
    // ---- decoded bit: first-argmin parity over previous q (cooperative) ----
    float a0, a1, b0, b1;
    upk2(qpA, a0, a1); upk2(qpB, b0, b1);
    float pA = (a1 < a0) ? 1.0f : 0.0f;  float vA = fminf(a0, a1);
    float pB = (b1 < b0) ? 1.0f : 0.0f;  float vB = fminf(b0, b1);
    float pH = (vB < vA) ? pB : pA;      float vH = fminf(vA, vB);
    float vO = shflx(vH);
    float pO = shflx(pH);
    float par = (vO < vH) ? pO : pH;     // even lane: own = low half (left
                                         // priority) -> exact first-index

    // ---- metric update: 8 trellis states of this half, packed pairwise ----
    u64 y2 = pk2(yt, yt);
    u64 d0 = add2(y2, sp0); u64 t0 = mul2(d0, d0);
    u64 p0 = fma2(t0, half2, negc2); u64 m0 = add2(qpA, p0);
    u64 d1 = add2(y2, sp1); u64 t1 = mul2(d1, d1);
    u64 p1 = fma2(t1, half2, negc2); u64 m1 = add2(qpB, p1);
    u64 d4 = add2(y2, sp4); u64 t4 = mul2(d4, d4);
    u64 p4 = fma2(t4, half2, negc2); u64 m4 = add2(qpA, p4);
    u64 d5 = add2(y2, sp5); u64 t5 = mul2(d5, d5);
    u64 p5 = fma2(t5, half2, negc2); u64 m5 = add2(qpB, p5);

    float x0, x1;
    upk2(m0, x0, x1); float olo0 = fminf(x0, x1);  // even: out0 | odd: out2
    upk2(m1, x0, x1); float olo1 = fminf(x0, x1);  // even: out1 | odd: out3
    upk2(m4, x0, x1); float ohi0 = fminf(x0, x1);  // even: out4 | odd: out6
    upk2(m5, x0, x1); float ohi1 = fminf(x0, x1);  // even: out5 | odd: out7

    // ---- exchange: even sends (out4,out5), odd sends (out2,out3) ----
    float sa = half ? olo0 : ohi0;
    float sb = half ? olo1 : ohi1;
    float ra = shflx(sa);
    float rb = shflx(sb);

    // even: qpA=(out0,out1), qpB=recv=(out2,out3)
    // odd:  qpA=recv=(out4,out5), qpB=(out6,out7)
    float ax = half ? ra : olo0;
    float ay = half ? rb : olo1;
    float bx = half ? ohi0 : ra;
    float by = half ? ohi1 : rb;
    qpA = pk2(ax, ay);
    qpB = pk2(bx, by);
    return par;
}

__global__ void __launch_bounds__(32, 1)
viterbi_pair_kernel(const float* __restrict__ y,
                    const float* __restrict__ h,
                    float* __restrict__ out) {
    int lane = threadIdx.x & 31;
    int half = lane & 1;                      // 0: q0..3, 1: q4..7
    int row  = blockIdx.x * 16 + (lane >> 1); // 16 rows per warp

    // sp[s] = sum_j (+-1)*h[j], exact products, left-to-right adds; negated.
    float h0 = h[0], h1 = h[1], h2 = h[2], h3 = h[3];
    float spn[16];
#pragma unroll
    for (int s = 0; s < 16; s++) {
        float s3 = ((s >> 3) & 1) ? -1.0f : 1.0f;  // MSB first (shifts 3,2,1,0)
        float s2 = ((s >> 2) & 1) ? -1.0f : 1.0f;
        float s1 = ((s >> 1) & 1) ? -1.0f : 1.0f;
        float s0 = ((s >> 0) & 1) ? -1.0f : 1.0f;
        float sp = __fadd_rn(
                       __fadd_rn(
                           __fadd_rn(__fmul_rn(s3, h0), __fmul_rn(s2, h1)),
                           __fmul_rn(s1, h2)),
                       __fmul_rn(s0, h3));
        spn[s] = -sp;
    }
    // state-pair indices owned by this lane: even {0,1,4,5}, odd {2,3,6,7}
    int pb = half ? 2 : 0;
    u64 sp0 = pk2(spn[2 * (pb + 0)], spn[2 * (pb + 0) + 1]);
    u64 sp1 = pk2(spn[2 * (pb + 1)], spn[2 * (pb + 1) + 1]);
    u64 sp4 = pk2(spn[2 * (pb + 4)], spn[2 * (pb + 4) + 1]);
    u64 sp5 = pk2(spn[2 * (pb + 5)], spn[2 * (pb + 5) + 1]);
    u64 half2 = pk2(0.5f, 0.5f);
    u64 negc2 = pk2(NEG_LOG_SQRT_2PI, NEG_LOG_SQRT_2PI);

    u64 qpA = 0ull;  // (+0.0f, +0.0f)
    u64 qpB = 0ull;

    const float4* yv = reinterpret_cast<const float4*>(y + (size_t)row * T_LEN);
    float4*       ov = reinterpret_cast<float4*>(out + (size_t)row * T_LEN);

    float4 yy = yv[0];  // both lanes of a pair load same address (broadcast)
#pragma unroll 1
    for (int i = 0; i < T_LEN / 4; i++) {
        // L2 prefetch one 128B line (8 float4 iters = 32 steps) ahead
        if (i + 8 < T_LEN / 4)
            asm volatile("prefetch.global.L2 [%0];" :: "l"(yv + i + 8));
        // register prefetch next iteration's data (distance 1)
        float4 yn;
        if (i + 1 < T_LEN / 4) yn = yv[i + 1];
        float4 d;
        d.x = vstep(qpA, qpB, sp0, sp1, sp4, sp5, half2, negc2, half, yy.x);
        d.y = vstep(qpA, qpB, sp0, sp1, sp4, sp5, half2, negc2, half, yy.y);
        d.z = vstep(qpA, qpB, sp0, sp1, sp4, sp5, half2, negc2, half, yy.z);
        d.w = vstep(qpA, qpB, sp0, sp1, sp4, sp5, half2, negc2, half, yy.w);
        if (half == 0) ov[i] = d;  // even lanes hold the valid decisions
        yy = yn;
    }
}

extern "C" void kernel_launch(void* const* d_in, const int* in_sizes, int n_in,
                              void* d_out, int out_size) {
    const float* y = (const float*)d_in[0];
    const float* h = (const float*)d_in[1];
    // d_in[2] = transition_table: fixed trellis tt[s] = [2s%16, (2s+1)%16], hardcoded.
    float* out = (float*)d_out;
    viterbi_pair_kernel<<<B_ROWS / 16, 32>>>(y, h, out);
}